// round 5
// baseline (speedup 1.0000x reference)
#include <cuda_runtime.h>
#include <cstdint>
#include <cstddef>

// Problem shape (fixed by setup_inputs): B=8, L=4096, D=1024, DK=1024
#define BATCH 8
#define SEQ   4096
#define DIM   1024
#define NCOLS 2048            // 2*DK
#define BL    (BATCH * SEQ)   // 32768 rows

// ---------------------------------------------------------------------------
// Scratch (no cudaMalloc allowed) — __device__ globals.
// ---------------------------------------------------------------------------
__device__ float g_qk[(size_t)BL * NCOLS];   // 256 MiB: [q | k] per token
__device__ float g_probs[BL];
__device__ int   g_bpos[BL];                 // compacted boundary positions per batch row
__device__ int   g_nc[BATCH];
__device__ float g_aux[BATCH];

// ---------------------------------------------------------------------------
// Packed fp32x2 FMA (sm_100+/sm_103a). Per-lane IEEE rn — bit-identical to
// two scalar fmaf, but one issue slot for two FMAs.
// ---------------------------------------------------------------------------
union F2U { float2 f; unsigned long long u; };

__device__ __forceinline__ void fma2(unsigned long long& c,
                                     unsigned long long a,
                                     unsigned long long b) {
    asm("fma.rn.f32x2 %0, %1, %2, %0;" : "+l"(c) : "l"(a), "l"(b));
}

// ---------------------------------------------------------------------------
// Kernel 1: fp32 GEMM  g_qk[BL, NCOLS] = tokens[BL, DIM] @ W[DIM, NCOLS]
// 128x128x16 tile, 256 threads, 8x8 micro-tile, FFMA2 inner product.
// ---------------------------------------------------------------------------
__global__ void __launch_bounds__(256, 2)
sgemm_kernel(const float* __restrict__ A, const float* __restrict__ W)
{
    __shared__ float As[16][128];   // transposed A tile: As[k][m]
    __shared__ float Bs[16][128];   // Bs[k][n]

    const int tid = threadIdx.x;
    const int bm  = blockIdx.y * 128;
    const int bn  = blockIdx.x * 128;

    // A tile loads: 128x16 floats = 512 float4, 2 per thread
    const int arow = tid >> 2;          // 0..63
    const int acol = (tid & 3) << 2;    // 0,4,8,12
    // B tile loads: 16x128 floats = 512 float4, 2 per thread
    const int brow = tid >> 5;          // 0..7
    const int bcol = (tid & 31) << 2;   // 0..124

    const int tx = tid & 15;            // column group
    const int ty = tid >> 4;            // row group

    unsigned long long acc[8][4];
#pragma unroll
    for (int i = 0; i < 8; i++)
#pragma unroll
        for (int j = 0; j < 4; j++) acc[i][j] = 0ull;

    for (int k0 = 0; k0 < DIM; k0 += 16) {
#pragma unroll
        for (int i = 0; i < 2; i++) {
            int r = arow + i * 64;
            float4 v = *reinterpret_cast<const float4*>(
                A + (size_t)(bm + r) * DIM + k0 + acol);
            As[acol + 0][r] = v.x;
            As[acol + 1][r] = v.y;
            As[acol + 2][r] = v.z;
            As[acol + 3][r] = v.w;
        }
#pragma unroll
        for (int i = 0; i < 2; i++) {
            int r = brow + i * 8;
            *reinterpret_cast<float4*>(&Bs[r][bcol]) =
                *reinterpret_cast<const float4*>(
                    W + (size_t)(k0 + r) * NCOLS + bn + bcol);
        }
        __syncthreads();

#pragma unroll
        for (int k = 0; k < 16; k++) {
            float a[8];
#pragma unroll
            for (int i = 0; i < 8; i++) a[i] = As[k][ty * 8 + i];
            unsigned long long b2[4];
#pragma unroll
            for (int j = 0; j < 4; j++)
                b2[j] = *reinterpret_cast<const unsigned long long*>(
                    &Bs[k][tx * 8 + j * 2]);
#pragma unroll
            for (int i = 0; i < 8; i++) {
                F2U au; au.f = make_float2(a[i], a[i]);
#pragma unroll
                for (int j = 0; j < 4; j++) fma2(acc[i][j], au.u, b2[j]);
            }
        }
        __syncthreads();
    }

    // Store 8x8 per thread as 2x float4 per row
#pragma unroll
    for (int i = 0; i < 8; i++) {
        float* cp = g_qk + (size_t)(bm + ty * 8 + i) * NCOLS + bn + tx * 8;
        F2U u0, u1, u2, u3;
        u0.u = acc[i][0]; u1.u = acc[i][1]; u2.u = acc[i][2]; u3.u = acc[i][3];
        *reinterpret_cast<float4*>(cp)     = make_float4(u0.f.x, u0.f.y, u1.f.x, u1.f.y);
        *reinterpret_cast<float4*>(cp + 4) = make_float4(u2.f.x, u2.f.y, u3.f.x, u3.f.y);
    }
}

// ---------------------------------------------------------------------------
// Kernel 2: one warp per token — cosine(q_l, k_{l-1}) -> probs
// ---------------------------------------------------------------------------
__global__ void cos_kernel(const float* __restrict__ start_key)
{
    const int gw   = (blockIdx.x * blockDim.x + threadIdx.x) >> 5;
    const int lane = threadIdx.x & 31;
    if (gw >= BL) return;
    const int l = gw & (SEQ - 1);

    const float4* q = reinterpret_cast<const float4*>(g_qk + (size_t)gw * NCOLS);
    const float4* kp = (l == 0)
        ? reinterpret_cast<const float4*>(start_key)
        : reinterpret_cast<const float4*>(g_qk + (size_t)(gw - 1) * NCOLS + DIM);

    float dot = 0.f, qq = 0.f, kk = 0.f;
#pragma unroll
    for (int i = 0; i < 8; i++) {
        float4 qv = q[lane + i * 32];
        float4 kv = kp[lane + i * 32];
        dot += qv.x * kv.x + qv.y * kv.y + qv.z * kv.z + qv.w * kv.w;
        qq  += qv.x * qv.x + qv.y * qv.y + qv.z * qv.z + qv.w * qv.w;
        kk  += kv.x * kv.x + kv.y * kv.y + kv.z * kv.z + kv.w * kv.w;
    }
#pragma unroll
    for (int o = 16; o; o >>= 1) {
        dot += __shfl_xor_sync(0xffffffffu, dot, o);
        qq  += __shfl_xor_sync(0xffffffffu, qq,  o);
        kk  += __shfl_xor_sync(0xffffffffu, kk,  o);
    }
    if (lane == 0) {
        float qn = fmaxf(sqrtf(qq), 1e-8f);
        float kn = fmaxf(sqrtf(kk), 1e-8f);
        float cs = dot / (qn * kn);
        g_probs[gw] = (1.0f - cs) * 0.5f;
    }
}

// ---------------------------------------------------------------------------
// Kernel 3: per-batch boundary scan/compaction, chunk_lens, aux-loss partial.
// 1 block per batch, 1024 threads, 4 positions each (L = 4096).
// ---------------------------------------------------------------------------
__global__ void __launch_bounds__(1024, 1)
scan_kernel(float* __restrict__ out_cl)
{
    const int b   = blockIdx.x;
    const int tid = threadIdx.x;
    const int lane = tid & 31, wid = tid >> 5;

    __shared__ int   warp_c[32];
    __shared__ float warp_s[32];
    __shared__ int   s_nc;
    __shared__ float s_G;

    const float* pr = g_probs + b * SEQ;
    float4 p4 = reinterpret_cast<const float4*>(pr)[tid];
    float p[4] = {p4.x, p4.y, p4.z, p4.w};

    int   m[4];
    int   cnt  = 0;
    float psum = 0.f;
#pragma unroll
    for (int i = 0; i < 4; i++) {
        int l = tid * 4 + i;
        m[i] = (p[i] > 0.5f) || (l == 0);
        cnt  += m[i];
        psum += p[i];
    }

    // warp inclusive scan of counts + warp sum of probs
    int inc = cnt;
#pragma unroll
    for (int o = 1; o < 32; o <<= 1) {
        int v = __shfl_up_sync(0xffffffffu, inc, o);
        if (lane >= o) inc += v;
    }
    float ws = psum;
#pragma unroll
    for (int o = 16; o; o >>= 1) ws += __shfl_xor_sync(0xffffffffu, ws, o);

    if (lane == 31) warp_c[wid] = inc;   // warp total
    if (lane == 0)  warp_s[wid] = ws;
    __syncthreads();

    if (wid == 0) {
        int v  = warp_c[lane];
        int iv = v;
#pragma unroll
        for (int o = 1; o < 32; o <<= 1) {
            int t = __shfl_up_sync(0xffffffffu, iv, o);
            if (lane >= o) iv += t;
        }
        float s = warp_s[lane];
#pragma unroll
        for (int o = 16; o; o >>= 1) s += __shfl_xor_sync(0xffffffffu, s, o);
        warp_c[lane] = iv - v;           // exclusive warp offsets
        if (lane == 31) s_nc = iv;       // total boundary count
        if (lane == 0)  s_G  = s;        // sum of probs
    }
    __syncthreads();

    // compact boundary positions
    int r = warp_c[wid] + (inc - cnt);
#pragma unroll
    for (int i = 0; i < 4; i++) {
        if (m[i]) { g_bpos[b * SEQ + r] = tid * 4 + i; r++; }
    }
    const int nc = s_nc;
    if (tid == 0) {
        g_nc[b] = nc;
        float G  = s_G / (float)SEQ;
        float Fm = (float)nc / (float)SEQ;
        // N/(N-1) * ((N-1)*Fm*G + (1-Fm)*(1-G)), N = 6
        g_aux[b] = 1.2f * (5.0f * Fm * G + (1.0f - Fm) * (1.0f - G));
    }
    __syncthreads();   // all g_bpos visible

    // chunk_lens (as float, pads -> 0)
#pragma unroll
    for (int i = 0; i < 4; i++) {
        int j = tid * 4 + i;
        float v = 0.f;
        if (j < nc) {
            int pj = g_bpos[b * SEQ + j];
            int pn = (j + 1 < nc) ? g_bpos[b * SEQ + j + 1] : SEQ;
            v = (float)(pn - pj);
        }
        out_cl[b * SEQ + j] = v;
    }
}

// ---------------------------------------------------------------------------
// Kernel 4: downsampled gather (tokens[boundary] * probs[boundary], zero pad)
// + scalar loss. One block per output row, 128 threads, 2 float4 each.
// ---------------------------------------------------------------------------
__global__ void gather_kernel(const float* __restrict__ tokens,
                              float* __restrict__ out_ds,
                              float* __restrict__ out_loss)
{
    const int row = blockIdx.x;          // 0..BL-1
    const int b   = row >> 12;           // / SEQ
    const int j   = row & (SEQ - 1);
    const int tid = threadIdx.x;

    float4* dst = reinterpret_cast<float4*>(out_ds + (size_t)row * DIM);
    if (j < g_nc[b]) {
        int   p = g_bpos[b * SEQ + j];
        float s = g_probs[b * SEQ + p];
        const float4* src = reinterpret_cast<const float4*>(
            tokens + (size_t)(b * SEQ + p) * DIM);
        float4 v0 = src[tid], v1 = src[tid + 128];
        dst[tid]       = make_float4(v0.x * s, v0.y * s, v0.z * s, v0.w * s);
        dst[tid + 128] = make_float4(v1.x * s, v1.y * s, v1.z * s, v1.w * s);
    } else {
        float4 z = make_float4(0.f, 0.f, 0.f, 0.f);
        dst[tid] = z; dst[tid + 128] = z;
    }

    if (row == 0 && tid == 0) {
        float s = 0.f;
#pragma unroll
        for (int i = 0; i < BATCH; i++) s += g_aux[i];
        *out_loss = s * (0.03f / (float)BATCH);   // mean * RATIO_LOSS_WEIGHT
    }
}

// ---------------------------------------------------------------------------
// Launch
// ---------------------------------------------------------------------------
extern "C" void kernel_launch(void* const* d_in, const int* in_sizes, int n_in,
                              void* d_out, int out_size)
{
    const float* tokens    = (const float*)d_in[0];   // [8,4096,1024]
    const float* W_qk      = (const float*)d_in[1];   // [1024,2048]
    const float* start_key = (const float*)d_in[2];   // [1024]

    float* out      = (float*)d_out;
    float* out_ds   = out;                        // [B, L, D]
    float* out_cl   = out + (size_t)BL * DIM;     // [B, L]
    float* out_loss = out_cl + BL;                // [1]

    dim3 gemm_grid(NCOLS / 128, BL / 128);        // 16 x 256
    sgemm_kernel<<<gemm_grid, 256>>>(tokens, W_qk);
    cos_kernel<<<BL / 8, 256>>>(start_key);       // 1 warp / token
    scan_kernel<<<BATCH, 1024>>>(out_cl);
    gather_kernel<<<BL, 128>>>(tokens, out_ds, out_loss);

    (void)in_sizes; (void)n_in; (void)out_size;
}

// round 8
// speedup vs baseline: 1.2457x; 1.2457x over previous
#include <cuda_runtime.h>
#include <cstdint>
#include <cstddef>

// Problem shape (fixed): B=8, L=4096, D=1024, DK=1024
#define BATCH 8
#define SEQ   4096
#define DIM   1024
#define NCOLS 2048
#define NROWS (BATCH * SEQ)               // 32768

// GEMM tiling: block 128x128, BK=16, 8 warps (4M x 2N), warp tile 32x64
#define BK    16
#define PAD   136                         // floats per k-row (128 + 8)
#define KROW  PAD
#define STG   (4 * BK * PAD)              // floats per stage = 8704
#define OFF_AH 0
#define OFF_AL (BK * PAD)
#define OFF_BH (2 * BK * PAD)
#define OFF_BL (3 * BK * PAD)
#define SMEM_BYTES (2 * STG * 4)          // 69632

// ---------------------------------------------------------------------------
// Scratch (no cudaMalloc allowed)
// ---------------------------------------------------------------------------
__device__ float g_qk[(size_t)NROWS * NCOLS];   // 256 MiB: [q | k] per token
__device__ float g_probs[NROWS];
__device__ int   g_bpos[NROWS];
__device__ int   g_nc[BATCH];
__device__ float g_aux[BATCH];

// ---------------------------------------------------------------------------
// Helpers
// ---------------------------------------------------------------------------
__device__ __forceinline__ float tf32_rna(float a) {
    float r;
    asm("cvt.rna.tf32.f32 %0, %1;" : "=f"(r) : "f"(a));
    return r;
}

// d += a(16x8 tf32) * b(8x8 tf32), fp32 accumulate
__device__ __forceinline__ void mma8(float* d, const uint32_t* a, const uint32_t* b) {
    asm volatile(
        "mma.sync.aligned.m16n8k8.row.col.f32.tf32.tf32.f32 "
        "{%0,%1,%2,%3}, {%4,%5,%6,%7}, {%8,%9}, {%0,%1,%2,%3};"
        : "+f"(d[0]), "+f"(d[1]), "+f"(d[2]), "+f"(d[3])
        : "r"(a[0]), "r"(a[1]), "r"(a[2]), "r"(a[3]), "r"(b[0]), "r"(b[1]));
}

// ---------------------------------------------------------------------------
// Kernel 1: 3xTF32 mma.sync GEMM   g_qk[NROWS,NCOLS] = tokens @ W
// grid (NCOLS/128=16, NROWS/128=256), 256 threads
// ---------------------------------------------------------------------------
__global__ void __launch_bounds__(256, 1)
gemm_mma(const float* __restrict__ A, const float* __restrict__ W)
{
    extern __shared__ float sm[];

    const int tid  = threadIdx.x;
    const int lane = tid & 31;
    const int wid  = tid >> 5;
    const int wm   = wid & 3;             // M group of 32 rows
    const int wn   = wid >> 2;            // N group of 64 cols
    const int bm   = blockIdx.y * 128;
    const int bn   = blockIdx.x * 128;

    float acc[2][8][4];
#pragma unroll
    for (int mt = 0; mt < 2; mt++)
#pragma unroll
        for (int nt = 0; nt < 8; nt++)
#pragma unroll
            for (int j = 0; j < 4; j++) acc[mt][nt][j] = 0.f;

    float4 va[2], vb[2];

    auto load_regs = [&](int k0) {
#pragma unroll
        for (int i = 0; i < 2; i++) {
            const int idx = tid + i * 256;
            va[i] = *reinterpret_cast<const float4*>(
                A + (size_t)(bm + (idx >> 2)) * DIM + k0 + (idx & 3) * 4);
            vb[i] = *reinterpret_cast<const float4*>(
                W + (size_t)(k0 + (idx >> 5)) * NCOLS + bn + (idx & 31) * 4);
        }
    };

    auto store_smem = [&](int buf) {
        float* base = sm + buf * STG;
#pragma unroll
        for (int i = 0; i < 2; i++) {
            const int idx = tid + i * 256;
            // A: transpose to [k][m] with PAD stride, split hi/lo
            {
                const int m = idx >> 2, kq = idx & 3;
                float e[4] = {va[i].x, va[i].y, va[i].z, va[i].w};
#pragma unroll
                for (int j = 0; j < 4; j++) {
                    float h = tf32_rna(e[j]);
                    float l = tf32_rna(e[j] - h);
                    base[OFF_AH + (kq * 4 + j) * KROW + m] = h;
                    base[OFF_AL + (kq * 4 + j) * KROW + m] = l;
                }
            }
            // B: already [k][n], split hi/lo, vector stores
            {
                const int k = idx >> 5, n = (idx & 31) * 4;
                float4 h, l;
                h.x = tf32_rna(vb[i].x); l.x = tf32_rna(vb[i].x - h.x);
                h.y = tf32_rna(vb[i].y); l.y = tf32_rna(vb[i].y - h.y);
                h.z = tf32_rna(vb[i].z); l.z = tf32_rna(vb[i].z - h.z);
                h.w = tf32_rna(vb[i].w); l.w = tf32_rna(vb[i].w - h.w);
                *reinterpret_cast<float4*>(base + OFF_BH + k * KROW + n) = h;
                *reinterpret_cast<float4*>(base + OFF_BL + k * KROW + n) = l;
            }
        }
    };

    load_regs(0);
    store_smem(0);
    __syncthreads();

    const int g  = lane >> 2;   // groupID
    const int tg = lane & 3;    // threadID_in_group

    for (int s = 0; s < DIM / BK; s++) {
        const int buf = s & 1;
        if (s + 1 < DIM / BK) load_regs((s + 1) * BK);

        const float* base = sm + buf * STG;
#pragma unroll
        for (int ks = 0; ks < BK; ks += 8) {
            const int o1 = (ks + tg) * KROW;
            const int o2 = (ks + 4 + tg) * KROW;

            uint32_t ah[2][4], al[2][4], bh[8][2], bl[8][2];
            const uint32_t* pAH = reinterpret_cast<const uint32_t*>(base + OFF_AH);
            const uint32_t* pAL = reinterpret_cast<const uint32_t*>(base + OFF_AL);
            const uint32_t* pBH = reinterpret_cast<const uint32_t*>(base + OFF_BH);
            const uint32_t* pBL = reinterpret_cast<const uint32_t*>(base + OFF_BL);

#pragma unroll
            for (int mt = 0; mt < 2; mt++) {
                const int m = wm * 32 + mt * 16 + g;
                ah[mt][0] = pAH[o1 + m];     ah[mt][1] = pAH[o1 + m + 8];
                ah[mt][2] = pAH[o2 + m];     ah[mt][3] = pAH[o2 + m + 8];
                al[mt][0] = pAL[o1 + m];     al[mt][1] = pAL[o1 + m + 8];
                al[mt][2] = pAL[o2 + m];     al[mt][3] = pAL[o2 + m + 8];
            }
#pragma unroll
            for (int nt = 0; nt < 8; nt++) {
                const int n = wn * 64 + nt * 8 + g;
                bh[nt][0] = pBH[o1 + n];     bh[nt][1] = pBH[o2 + n];
                bl[nt][0] = pBL[o1 + n];     bl[nt][1] = pBL[o2 + n];
            }

            // pass 1: hi*hi
#pragma unroll
            for (int nt = 0; nt < 8; nt++)
#pragma unroll
                for (int mt = 0; mt < 2; mt++) mma8(acc[mt][nt], ah[mt], bh[nt]);
            // pass 2: hi*lo
#pragma unroll
            for (int nt = 0; nt < 8; nt++)
#pragma unroll
                for (int mt = 0; mt < 2; mt++) mma8(acc[mt][nt], ah[mt], bl[nt]);
            // pass 3: lo*hi
#pragma unroll
            for (int nt = 0; nt < 8; nt++)
#pragma unroll
                for (int mt = 0; mt < 2; mt++) mma8(acc[mt][nt], al[mt], bh[nt]);
        }

        if (s + 1 < DIM / BK) store_smem(buf ^ 1);
        __syncthreads();
    }

    // Epilogue: C fragment -> g_qk
#pragma unroll
    for (int mt = 0; mt < 2; mt++) {
        const int r0 = bm + wm * 32 + mt * 16 + g;
#pragma unroll
        for (int nt = 0; nt < 8; nt++) {
            const int c = bn + wn * 64 + nt * 8 + tg * 2;
            *reinterpret_cast<float2*>(g_qk + (size_t)r0 * NCOLS + c) =
                make_float2(acc[mt][nt][0], acc[mt][nt][1]);
            *reinterpret_cast<float2*>(g_qk + (size_t)(r0 + 8) * NCOLS + c) =
                make_float2(acc[mt][nt][2], acc[mt][nt][3]);
        }
    }
}

// ---------------------------------------------------------------------------
// Kernel 2: one warp per token — cosine(q_l, k_{l-1}) -> probs
// ---------------------------------------------------------------------------
__global__ void cos_kernel(const float* __restrict__ start_key)
{
    const int gw   = (blockIdx.x * blockDim.x + threadIdx.x) >> 5;
    const int lane = threadIdx.x & 31;
    if (gw >= NROWS) return;
    const int l = gw & (SEQ - 1);

    const float4* q = reinterpret_cast<const float4*>(g_qk + (size_t)gw * NCOLS);
    const float4* kp = (l == 0)
        ? reinterpret_cast<const float4*>(start_key)
        : reinterpret_cast<const float4*>(g_qk + (size_t)(gw - 1) * NCOLS + DIM);

    float dot = 0.f, qq = 0.f, kk = 0.f;
#pragma unroll
    for (int i = 0; i < 8; i++) {
        float4 qv = q[lane + i * 32];
        float4 kv = kp[lane + i * 32];
        dot += qv.x * kv.x + qv.y * kv.y + qv.z * kv.z + qv.w * kv.w;
        qq  += qv.x * qv.x + qv.y * qv.y + qv.z * qv.z + qv.w * qv.w;
        kk  += kv.x * kv.x + kv.y * kv.y + kv.z * kv.z + kv.w * kv.w;
    }
#pragma unroll
    for (int o = 16; o; o >>= 1) {
        dot += __shfl_xor_sync(0xffffffffu, dot, o);
        qq  += __shfl_xor_sync(0xffffffffu, qq,  o);
        kk  += __shfl_xor_sync(0xffffffffu, kk,  o);
    }
    if (lane == 0) {
        float qn = fmaxf(sqrtf(qq), 1e-8f);
        float kn = fmaxf(sqrtf(kk), 1e-8f);
        float cs = dot / (qn * kn);
        g_probs[gw] = (1.0f - cs) * 0.5f;
    }
}

// ---------------------------------------------------------------------------
// Kernel 3: per-batch boundary scan/compaction, chunk_lens, aux partials
// ---------------------------------------------------------------------------
__global__ void __launch_bounds__(1024, 1)
scan_kernel(float* __restrict__ out_cl)
{
    const int b = blockIdx.x;
    const int tid = threadIdx.x;
    const int lane = tid & 31, wid = tid >> 5;

    __shared__ int   warp_c[32];
    __shared__ float warp_s[32];
    __shared__ int   s_nc;
    __shared__ float s_G;

    const float* pr = g_probs + b * SEQ;
    float4 p4 = reinterpret_cast<const float4*>(pr)[tid];
    float p[4] = {p4.x, p4.y, p4.z, p4.w};

    int m[4]; int cnt = 0; float psum = 0.f;
#pragma unroll
    for (int i = 0; i < 4; i++) {
        int l = tid * 4 + i;
        m[i] = (p[i] > 0.5f) || (l == 0);
        cnt += m[i];
        psum += p[i];
    }

    int inc = cnt;
#pragma unroll
    for (int o = 1; o < 32; o <<= 1) {
        int v = __shfl_up_sync(0xffffffffu, inc, o);
        if (lane >= o) inc += v;
    }
    float ws = psum;
#pragma unroll
    for (int o = 16; o; o >>= 1) ws += __shfl_xor_sync(0xffffffffu, ws, o);

    if (lane == 31) warp_c[wid] = inc;
    if (lane == 0)  warp_s[wid] = ws;
    __syncthreads();

    if (wid == 0) {
        int v = warp_c[lane];
        int iv = v;
#pragma unroll
        for (int o = 1; o < 32; o <<= 1) {
            int t = __shfl_up_sync(0xffffffffu, iv, o);
            if (lane >= o) iv += t;
        }
        float s = warp_s[lane];
#pragma unroll
        for (int o = 16; o; o >>= 1) s += __shfl_xor_sync(0xffffffffu, s, o);
        warp_c[lane] = iv - v;
        if (lane == 31) s_nc = iv;
        if (lane == 0)  s_G  = s;
    }
    __syncthreads();

    int r = warp_c[wid] + (inc - cnt);
#pragma unroll
    for (int i = 0; i < 4; i++) {
        if (m[i]) { g_bpos[b * SEQ + r] = tid * 4 + i; r++; }
    }
    const int nc = s_nc;
    if (tid == 0) {
        g_nc[b] = nc;
        float G  = s_G / (float)SEQ;
        float Fm = (float)nc / (float)SEQ;
        g_aux[b] = 1.2f * (5.0f * Fm * G + (1.0f - Fm) * (1.0f - G));
    }
    __syncthreads();

#pragma unroll
    for (int i = 0; i < 4; i++) {
        int j = tid * 4 + i;
        float v = 0.f;
        if (j < nc) {
            int pj = g_bpos[b * SEQ + j];
            int pn = (j + 1 < nc) ? g_bpos[b * SEQ + j + 1] : SEQ;
            v = (float)(pn - pj);
        }
        out_cl[b * SEQ + j] = v;
    }
}

// ---------------------------------------------------------------------------
// Kernel 4: downsampled gather + scalar loss
// ---------------------------------------------------------------------------
__global__ void gather_kernel(const float* __restrict__ tokens,
                              float* __restrict__ out_ds,
                              float* __restrict__ out_loss)
{
    const int row = blockIdx.x;
    const int b = row >> 12;
    const int j = row & (SEQ - 1);
    const int tid = threadIdx.x;

    float4* dst = reinterpret_cast<float4*>(out_ds + (size_t)row * DIM);
    if (j < g_nc[b]) {
        int   p = g_bpos[b * SEQ + j];
        float s = g_probs[b * SEQ + p];
        const float4* src = reinterpret_cast<const float4*>(
            tokens + (size_t)(b * SEQ + p) * DIM);
        float4 v0 = src[tid], v1 = src[tid + 128];
        dst[tid]       = make_float4(v0.x * s, v0.y * s, v0.z * s, v0.w * s);
        dst[tid + 128] = make_float4(v1.x * s, v1.y * s, v1.z * s, v1.w * s);
    } else {
        float4 z = make_float4(0.f, 0.f, 0.f, 0.f);
        dst[tid] = z; dst[tid + 128] = z;
    }

    if (row == 0 && tid == 0) {
        float s = 0.f;
#pragma unroll
        for (int i = 0; i < BATCH; i++) s += g_aux[i];
        *out_loss = s * (0.03f / (float)BATCH);
    }
}

// ---------------------------------------------------------------------------
// Launch
// ---------------------------------------------------------------------------
extern "C" void kernel_launch(void* const* d_in, const int* in_sizes, int n_in,
                              void* d_out, int out_size)
{
    const float* tokens    = (const float*)d_in[0];
    const float* W_qk      = (const float*)d_in[1];
    const float* start_key = (const float*)d_in[2];

    float* out      = (float*)d_out;
    float* out_ds   = out;
    float* out_cl   = out + (size_t)NROWS * DIM;
    float* out_loss = out_cl + NROWS;

    cudaFuncSetAttribute(gemm_mma, cudaFuncAttributeMaxDynamicSharedMemorySize,
                         SMEM_BYTES);

    dim3 grid(NCOLS / 128, NROWS / 128);   // (16, 256)
    gemm_mma<<<grid, 256, SMEM_BYTES>>>(tokens, W_qk);
    cos_kernel<<<NROWS / 8, 256>>>(start_key);
    scan_kernel<<<BATCH, 1024>>>(out_cl);
    gather_kernel<<<NROWS, 128>>>(tokens, out_ds, out_loss);

    (void)in_sizes; (void)n_in; (void)out_size;
}